// round 13
// baseline (speedup 1.0000x reference)
#include <cuda_runtime.h>
#include <cstdint>

#define Nn 2048
#define Dd 64
#define Vv 2048
#define TB 128                      // pair tile dim
#define NT (Nn / TB)                // 16
#define NTILES (NT * (NT + 1) / 2)  // 136 triangle tiles
#define PADK 33                     // float2 row stride (pad) -> conflict-free
#define NTHR 512
#define PREB 256                    // k_pre max blocks (256*512*8 f4 = 16MB)

// Scratch (no allocations -> __device__ globals). All overwritten per call;
// g_ctr self-resets each run.
__device__ float g_part[PREB];              // per-block maxes of map
__device__ float g_rowsum[Nn];              // S[i] = sum_d emb[i][d]
__device__ float g_psum[NTILES], g_pcnt[NTILES];
__device__ unsigned g_ctr;                  // zero-init

// ---------------------------------------------------------------------------
// blocks 0..255: map max, 8 front-batched float4/thread (MLP 8)
// blocks 256..259: row sums of emb (one row per thread, 512 rows/block)
__global__ __launch_bounds__(512) void k_pre(const float4* __restrict__ mapd,
                                             const float4* __restrict__ emb) {
    int bid = blockIdx.x, tid = threadIdx.x;
    if (bid < PREB) {
        const float4* p = mapd + (size_t)bid * 4096;   // 512 thr * 8 f4
        float4 x[8];
#pragma unroll
        for (int k = 0; k < 8; k++) x[k] = p[tid + 512 * k];
        float v = 0.0f;
#pragma unroll
        for (int k = 0; k < 8; k++)
            v = fmaxf(v, fmaxf(fmaxf(x[k].x, x[k].y), fmaxf(x[k].z, x[k].w)));
#pragma unroll
        for (int o = 16; o; o >>= 1)
            v = fmaxf(v, __shfl_xor_sync(0xffffffffu, v, o));
        __shared__ float sred[16];
        int lane = tid & 31, w = tid >> 5;
        if (lane == 0) sred[w] = v;
        __syncthreads();
        if (tid == 0) {
            float m = sred[0];
#pragma unroll
            for (int i = 1; i < 16; i++) m = fmaxf(m, sred[i]);
            g_part[bid] = m;
        }
    } else {
        int row = (bid - PREB) * 512 + tid;            // 2048 rows / 4 blocks
        const float4* e = emb + row * (Dd / 4);
        float s = 0.0f;
#pragma unroll
        for (int k = 0; k < Dd / 4; k++) {
            float4 x = e[k];
            s += (x.x + x.y) + (x.z + x.w);
        }
        g_rowsum[row] = s;
    }
}

// ---------------------------------------------------------------------------
extern __shared__ unsigned long long smem_raw[];

// 512 threads, 128x128 tile; thread (tx=tid&15, ty=tid>>4) owns rows
// ty+32r (r<4), cols tx+16c (c<8). Sum|a-b| = 2*Sum max - S_i - S_j
// (FMNMX on alu pipe + FADD on fma pipe, balanced dual-pipe).
// Tableless: 4 chunks of [16 dual reg-gathers -> 8 k2-steps -> combine to
// SMEM met planes]; gather latency hides under ~1100 issue-slots of math.
// Last finishing block folds the global reduction.
__global__ __launch_bounds__(NTHR, 1) void k_main(const int* __restrict__ ids,
                                                  const float2* __restrict__ emb,
                                                  const float* __restrict__ tree,
                                                  const float* __restrict__ mapd,
                                                  float* __restrict__ out) {
    int tid = threadIdx.x, bid = blockIdx.x;
    int t = bid, bi = 0;
    while (t >= NT - bi) { t -= NT - bi; bi++; }
    int bj = bi + t;
    int ibase = bi * TB, jbase = bj * TB;
    bool offdiag = (bi != bj);

    float2* sA = (float2*)smem_raw;                 // [128][PADK]
    float2* sB = sA + TB * PADK;
    int*   sIdI = (int*)(sB + TB * PADK);
    int*   sIdJ = sIdI + TB;
    float* sSA  = (float*)(sIdJ + TB);              // row sums i-tile
    float* sSB  = sSA + TB;                         // row sums j-tile
    float* sSc  = sSB + TB;                         // [0] = 0.5/max
    float* sred = sSc + 4;                          // [32]
    float* sMet = sred + 32;                        // [32][512] metric planes

    int tx = tid & 15, ty = tid >> 4;
    int lane = tid & 31, w = tid >> 5;

    // ---- prologue: ids, rowsums, tiles; warp 0 also folds g_part -> sc ----
    if (tid < TB)            sIdI[tid] = ids[ibase + tid];
    else if (tid < 2 * TB)   sIdJ[tid - TB] = ids[jbase + tid - TB];
    else if (tid < 3 * TB)   sSA[tid - 2 * TB] = g_rowsum[ibase + tid - 2 * TB];
    else                     sSB[tid - 3 * TB] = g_rowsum[jbase + tid - 3 * TB];
    if (tid < 32) {
        float v = 0.0f;
#pragma unroll
        for (int k = 0; k < PREB / 32; k++) v = fmaxf(v, g_part[tid + 32 * k]);
#pragma unroll
        for (int o = 16; o; o >>= 1)
            v = fmaxf(v, __shfl_xor_sync(0xffffffffu, v, o));
        if (tid == 0) sSc[0] = 0.5f / v;
    }
    for (int x = tid; x < TB * 32; x += NTHR) {
        int row = x >> 5, k2 = x & 31;
        sA[row * PADK + k2] = emb[(ibase + row) * 32 + k2];
        sB[row * PADK + k2] = emb[(jbase + row) * 32 + k2];
    }
    __syncthreads();

    float acc[4][8];
#pragma unroll
    for (int r = 0; r < 4; r++)
#pragma unroll
        for (int c = 0; c < 8; c++) acc[r][c] = 0.0f;

    const float2* sArow = sA + ty * PADK;
    const float2* sBrow = sB + tx * PADK;
    float sc = sSc[0];

    // ---- mainloop: 4 chunks of (16 dual gathers -> 8 k2 -> combine) ----
#pragma unroll
    for (int ch = 0; ch < 4; ch++) {
        float tr[8], mg[8];
        {
            size_t ro = (size_t)sIdI[ty + 32 * ch] * Vv;
            const float* tp = tree + ro;
            const float* mp = mapd + ro;
#pragma unroll
            for (int c = 0; c < 8; c++) {
                int idj = sIdJ[tx + 16 * c];
                asm volatile("ld.global.nc.f32 %0, [%1];"
                             : "=f"(tr[c]) : "l"(tp + idj));
                asm volatile("ld.global.nc.f32 %0, [%1];"
                             : "=f"(mg[c]) : "l"(mp + idj));
            }
        }
#pragma unroll
        for (int kk = 0; kk < 8; kk++) {
            int k2 = ch * 8 + kk;
            float2 b2[8];
#pragma unroll
            for (int c = 0; c < 8; c++) b2[c] = sBrow[(16 * c) * PADK + k2];
#pragma unroll
            for (int r = 0; r < 4; r++) {
                float2 a = sArow[(32 * r) * PADK + k2];
#pragma unroll
                for (int c = 0; c < 8; c++) {
                    acc[r][c] += fmaxf(a.x, b2[c].x);   // FMNMX + FADD
                    acc[r][c] += fmaxf(a.y, b2[c].y);
                }
            }
        }
#pragma unroll
        for (int c = 0; c < 8; c++)
            sMet[(ch * 8 + c) * NTHR + tid] = fmaf(sc, mg[c], 0.5f * tr[c]);
    }

    // ---- epilogue: ed = (2*sum(max) - S_i - S_j)/64 ----
    float loss = 0.0f, cnt = 0.0f;
    const float inv64 = 1.0f / 64.0f;
#pragma unroll
    for (int r = 0; r < 4; r++) {
        int ir = ty + 32 * r;
        int idi = sIdI[ir];
        int gi  = ibase + ir;
        float Si = sSA[ir];
#pragma unroll
        for (int c = 0; c < 8; c++) {
            int jc = tx + 16 * c;
            int idj = sIdJ[jc];
            int gj  = jbase + jc;
            if ((offdiag || gi < gj) && idi != idj) {
                float ed = (2.0f * acc[r][c] - Si - sSB[jc]) * inv64;
                loss += fabsf(ed - sMet[(r * 8 + c) * NTHR + tid]);
                cnt += 1.0f;
            }
        }
    }

#pragma unroll
    for (int o = 16; o; o >>= 1) {
        loss += __shfl_xor_sync(0xffffffffu, loss, o);
        cnt  += __shfl_xor_sync(0xffffffffu, cnt, o);
    }
    if (lane == 0) { sred[w] = loss; sred[16 + w] = cnt; }
    __syncthreads();
    if (tid == 0) {
        float L = 0.0f, C = 0.0f;
#pragma unroll
        for (int i = 0; i < 16; i++) { L += sred[i]; C += sred[16 + i]; }
        g_psum[bid] = L;
        g_pcnt[bid] = C;
        __threadfence();
        unsigned done = atomicAdd(&g_ctr, 1u);
        sred[0] = (done == NTILES - 1) ? 1.0f : 0.0f;
    }
    __syncthreads();
    if (sred[0] != 0.0f) {            // last block folds the final reduction
        __threadfence();
        float L = 0.0f, C = 0.0f;
        if (tid < NTILES) {
            L = *((volatile float*)g_psum + tid);
            C = *((volatile float*)g_pcnt + tid);
        }
#pragma unroll
        for (int o = 16; o; o >>= 1) {
            L += __shfl_xor_sync(0xffffffffu, L, o);
            C += __shfl_xor_sync(0xffffffffu, C, o);
        }
        if (lane == 0) { sred[w] = L; sred[16 + w] = C; }
        __syncthreads();
        if (tid == 0) {
            float LL = 0.0f, CC = 0.0f;
#pragma unroll
            for (int i = 0; i < 16; i++) { LL += sred[i]; CC += sred[16 + i]; }
            out[0] = LL / CC;
            g_ctr = 0u;               // self-reset for next graph replay
        }
    }
}

// ---------------------------------------------------------------------------
extern "C" void kernel_launch(void* const* d_in, const int* in_sizes, int n_in,
                              void* d_out, int out_size) {
    const int*   ids  = (const int*)d_in[0];
    const float* emb  = (const float*)d_in[1];
    const float* tree = (const float*)d_in[2];
    const float* mapd = (const float*)d_in[3];
    float* out = (float*)d_out;

    // tiles 67584 + aux ~2.2K + met planes 65536 ≈ 135.4KB
    const int SMEM_BYTES = 136 * 1024;
    cudaFuncSetAttribute(k_main, cudaFuncAttributeMaxDynamicSharedMemorySize,
                         SMEM_BYTES);

    k_pre<<<PREB + 4, 512>>>((const float4*)mapd, (const float4*)emb);
    k_main<<<NTILES, NTHR, SMEM_BYTES>>>(ids, (const float2*)emb, tree, mapd,
                                         out);
}